// round 13
// baseline (speedup 1.0000x reference)
#include <cuda_runtime.h>
#include <cooperative_groups.h>
#include <cstdint>
#include <cstddef>

namespace cg = cooperative_groups;

#define TN 2048
#define BN 256
#define DN 40
#define HN 128
#define CN 35
#define TDN (TN * DN)

// cluster-path geometry
#define CSIZE  8
#define C_NCTA 128          // 16 clusters x 8 CTAs
#define C_NTHR 512
#define GB 16               // batch rows per cluster
#define UPC 16              // units per CTA (per layer)

// fallback geometry (R8)
#define F_NCTA 128
#define F_NTHR 256

// ---------------------------------------------------------------------------
// Shared helpers.
union F2U { float2 f; unsigned long long u; };
__device__ __forceinline__ void ffma2(float2& acc, float2 a, float2 b) {
    F2U ua, ub, uc;
    ua.f = a; ub.f = b; uc.f = acc;
    asm("fma.rn.f32x2 %0, %1, %2, %0;" : "+l"(uc.u) : "l"(ua.u), "l"(ub.u));
    acc = uc.f;
}
__device__ __forceinline__ float sigf(float x)  { return 1.0f / (1.0f + __expf(-x)); }
__device__ __forceinline__ float tanhx(float x) {
    x = fminf(fmaxf(x, -15.f), 15.f);
    float e = __expf(2.f * x);
    return (e - 1.f) / (e + 1.f);
}

struct LstmArgs {
    const float *x;
    const int   *length;
    const float *Wih0, *Whh0, *bih0, *bhh0;
    const float *Wih1, *Whh1, *bih1, *bhh1;
    const float *lng, *lnb, *fcw, *fcb;
    float       *out;
};

// ===========================================================================
// CLUSTER PATH — 16 independent clusters of 8 CTAs; recurrence via DSMEM.
// ===========================================================================
struct alignas(16) SmemC {
    float4 wx [UPC][DN];     // L0 W_ih  {Wi,Wf,Wg,Wo}
    float4 wh0[UPC][HN];     // L0 W_hh
    float4 w1i[UPC][HN];     // L1 W_ih
    float4 w1h[UPC][HN];     // L1 W_hh
    float4 sb [2][UPC];      // bias
    float  sxb[GB][44];      // x tile (40 padded to 44)
    float  sh0[2][HN][GB];   // h0 staged, double-buffered
    float  sh1[2][HN][GB];   // h1 staged, double-buffered
};
#define C_SMEM ((int)sizeof(SmemC))

__global__ void __launch_bounds__(C_NTHR, 1) lstm_cluster(LstmArgs a)
{
    extern __shared__ char smem_raw[];
    SmemC* sm = (SmemC*)smem_raw;
    cg::cluster_group cluster = cg::this_cluster();
    const int tid   = threadIdx.x;
    const int rank  = (int)cluster.block_rank();
    const int cid   = blockIdx.x / CSIZE;
    const int u0    = rank * UPC;
    const int bbase = cid * GB;

    // ---- phase 0: zero staged h, pack weights + bias ----
    {
        float* z0 = &sm->sh0[0][0][0];
        float* z1 = &sm->sh1[0][0][0];
        for (int i = tid; i < 2 * HN * GB; i += C_NTHR) { z0[i] = 0.f; z1[i] = 0.f; }

        for (int i = tid; i < UPC * DN; i += C_NTHR) {
            int u = i / DN, k = i - u * DN, r = u0 + u;
            sm->wx[u][k] = make_float4(a.Wih0[(0 * HN + r) * DN + k],
                                       a.Wih0[(1 * HN + r) * DN + k],
                                       a.Wih0[(2 * HN + r) * DN + k],
                                       a.Wih0[(3 * HN + r) * DN + k]);
        }
        for (int i = tid; i < UPC * HN; i += C_NTHR) {
            int u = i >> 7, k = i & 127, r = u0 + u;
            sm->wh0[u][k] = make_float4(a.Whh0[(0 * HN + r) * HN + k],
                                        a.Whh0[(1 * HN + r) * HN + k],
                                        a.Whh0[(2 * HN + r) * HN + k],
                                        a.Whh0[(3 * HN + r) * HN + k]);
            sm->w1i[u][k] = make_float4(a.Wih1[(0 * HN + r) * HN + k],
                                        a.Wih1[(1 * HN + r) * HN + k],
                                        a.Wih1[(2 * HN + r) * HN + k],
                                        a.Wih1[(3 * HN + r) * HN + k]);
            sm->w1h[u][k] = make_float4(a.Whh1[(0 * HN + r) * HN + k],
                                        a.Whh1[(1 * HN + r) * HN + k],
                                        a.Whh1[(2 * HN + r) * HN + k],
                                        a.Whh1[(3 * HN + r) * HN + k]);
        }
        if (tid < 32) {
            int s = tid >> 4, u = tid & 15, r = u0 + u;
            const float* bi = s ? a.bih1 : a.bih0;
            const float* bh = s ? a.bhh1 : a.bhh0;
            sm->sb[s][u] = make_float4(bi[0 * HN + r] + bh[0 * HN + r],
                                       bi[1 * HN + r] + bh[1 * HN + r],
                                       bi[2 * HN + r] + bh[2 * HN + r],
                                       bi[3 * HN + r] + bh[3 * HN + r]);
        }
    }

    // ---- per-thread roles: one (layer, unit, batch) cell each ----
    const int lane = tid & 31;
    const int wid  = tid >> 5;
    const int b    = lane & 15;
    const int ud   = lane >> 4;
    const int s    = wid >> 3;            // layer
    const int lu   = (wid & 7) * 2 + ud;  // local unit 0..15
    const int ug   = u0 + lu;             // global unit 0..127
    const int len  = a.length[bbase + b];
    const float4* w1p = s ? sm->w1i[lu] : sm->wx[lu];
    const float4* w2p = s ? sm->w1h[lu] : sm->wh0[lu];

    // DSMEM peer base pointers for this thread's h-destination array
    float* hb = s ? &sm->sh1[0][0][0] : &sm->sh0[0][0][0];
    float* pp[CSIZE];
#pragma unroll
    for (int r = 0; r < CSIZE; r++)
        pp[r] = cluster.map_shared_rank(hb, r);

    // x staging role: threads 0..159 (all layer-0 warps) stage the 16x40 tile
    const bool xst = tid < 160;
    const int  xb = tid / 10, xj = tid - xb * 10;
    float4 xr = make_float4(0.f, 0.f, 0.f, 0.f);
    if (xst)
        xr = __ldcg((const float4*)(a.x + (size_t)(bbase + xb) * TDN + xj * 4));

    __syncthreads();   // phase-0 SMEM writes visible CTA-wide BEFORE any read
    const float4 bias = sm->sb[s][lu];   // (R10/R11 bug: this read raced phase 0)
    cluster.sync();    // zeros + weights visible before any peer writes arrive

    float c = 0.f, h = 0.f;

    // ---- phase 1: step loop ----
#pragma unroll 1
    for (int it = 0; it <= TN; it++) {
        const int rp = it & 1;            // read parity
        const int wp = rp ^ 1;            // write parity

        if (it < TN && xst) {
            float* d = &sm->sxb[xb][xj * 4];
            d[0] = xr.x; d[1] = xr.y; d[2] = xr.z; d[3] = xr.w;
        }
        __syncthreads();

        const bool active = s ? (it >= 1) : (it < TN);
        if (active) {
            float2 aif = make_float2(bias.x, bias.y);
            float2 ago = make_float2(bias.z, bias.w);
            const float* h0r = &sm->sh0[rp][0][b];

            if (s == 0) {
                const float* xv = &sm->sxb[b][0];
#pragma unroll 4
                for (int k = 0; k < DN; k++) {
                    float v = xv[k]; float2 d = make_float2(v, v);
                    float4 w4 = w1p[k];
                    ffma2(aif, make_float2(w4.x, w4.y), d);
                    ffma2(ago, make_float2(w4.z, w4.w), d);
                }
#pragma unroll 4
                for (int k = 0; k < HN; k++) {
                    float v = h0r[k << 4]; float2 d = make_float2(v, v);
                    float4 w4 = w2p[k];
                    ffma2(aif, make_float2(w4.x, w4.y), d);
                    ffma2(ago, make_float2(w4.z, w4.w), d);
                }
            } else {
#pragma unroll 4
                for (int k = 0; k < HN; k++) {
                    float v = h0r[k << 4]; float2 d = make_float2(v, v);
                    float4 w4 = w1p[k];
                    ffma2(aif, make_float2(w4.x, w4.y), d);
                    ffma2(ago, make_float2(w4.z, w4.w), d);
                }
                const float* h1r = &sm->sh1[rp][0][b];
#pragma unroll 4
                for (int k = 0; k < HN; k++) {
                    float v = h1r[k << 4]; float2 d = make_float2(v, v);
                    float4 w4 = w2p[k];
                    ffma2(aif, make_float2(w4.x, w4.y), d);
                    ffma2(ago, make_float2(w4.z, w4.w), d);
                }
            }

            if (xst && it + 1 < TN)   // prefetch next x tile
                xr = __ldcg((const float4*)(a.x + (size_t)(bbase + xb) * TDN
                                            + (size_t)(it + 1) * DN + xj * 4));

            const int t = s ? (it - 1) : it;
            {
                float i_ = sigf(aif.x), f_ = sigf(aif.y);
                float g_ = tanhx(ago.x), o_ = sigf(ago.y);
                float cn = f_ * c + i_ * g_;
                float hn = o_ * tanhx(cn);
                if (t < len) { c = cn; h = hn; }
            }
            // push h into every CTA's staged buffer (write parity)
            const int idx = ((wp * HN + ug) << 4) + b;
#pragma unroll
            for (int r = 0; r < CSIZE; r++) pp[r][idx] = h;
        }
        cluster.sync();
    }

    // ---- phase 2: LN + FC head (2 batch rows per CTA, all data local) ----
    {
        float* hv  = &sm->sxb[0][0];
        float* red = hv + 136;
        const int wpar = (TN + 1) & 1;

        for (int rep = 0; rep < 2; rep++) {
            const int bl = rank * 2 + rep;
            float v = (tid < HN) ? sm->sh1[wpar][tid][bl] : 0.f;

            float sum = v;
#pragma unroll
            for (int o = 16; o; o >>= 1) sum += __shfl_xor_sync(0xffffffffu, sum, o);
            if ((tid & 31) == 0 && tid < HN) red[tid >> 5] = sum;
            __syncthreads();
            float mu = (red[0] + red[1] + red[2] + red[3]) * (1.0f / HN);

            float d = (tid < HN) ? (v - mu) : 0.f;
            float q = d * d;
#pragma unroll
            for (int o = 16; o; o >>= 1) q += __shfl_xor_sync(0xffffffffu, q, o);
            __syncthreads();
            if ((tid & 31) == 0 && tid < HN) red[tid >> 5] = q;
            __syncthreads();
            float var = (red[0] + red[1] + red[2] + red[3]) * (1.0f / HN);

            if (tid < HN)
                hv[tid] = d * rsqrtf(var + 1e-5f) * a.lng[tid] + a.lnb[tid];
            __syncthreads();

            if (tid < CN) {
                float acc = a.fcb[tid];
#pragma unroll 4
                for (int k = 0; k < HN; k++)
                    acc = fmaf(hv[k], a.fcw[tid * HN + k], acc);
                a.out[(bbase + bl) * CN + tid] = acc;
            }
            __syncthreads();
        }
    }
    cluster.sync();
}

// ===========================================================================
// FALLBACK PATH — R8 kernel verbatim (proven 16,580 us). Global-flag sync.
// ===========================================================================
__device__ __align__(16) float g_xT[TDN * BN];
__device__ __align__(16) float gf_h0[2][HN * BN];
__device__ __align__(16) float gf_h1[2][HN * BN];

struct alignas(128) BarSlot { unsigned v; };
__device__ BarSlot g_cnt;
__device__ volatile BarSlot g_phz;
__device__ __align__(128) unsigned g_flagF[4][32];

__device__ __forceinline__ unsigned ldacq(const unsigned* p) {
    unsigned v;
    asm volatile("ld.acquire.gpu.global.u32 %0, [%1];" : "=r"(v) : "l"(p) : "memory");
    return v;
}
__device__ __forceinline__ void strel(unsigned* p, unsigned v) {
    asm volatile("st.release.gpu.global.u32 [%0], %1;" :: "l"(p), "r"(v) : "memory");
}
__device__ __forceinline__ void gbar_full() {
    __syncthreads();
    if (threadIdx.x == 0) {
        unsigned ph = g_phz.v;
        __threadfence();
        if (atomicAdd(&g_cnt.v, 1u) == F_NCTA - 1u) {
            g_cnt.v = 0u;
            __threadfence();
            g_phz.v = ph + 1u;
        } else {
            while (g_phz.v == ph) { }
            __threadfence();
        }
    }
    __syncthreads();
}

struct alignas(16) SmemF {
    float2 wx [4][DN][2];
    float2 wh0[4][HN][2];
    float2 w1i[4][HN][2];
    float2 w1h[4][HN][2];
    float2 sb[2][4][2];
    float  sx [DN * 64];
    float  sh0[HN * 64];
    float  sh1[HN * 64];
    float2 red[4][32][8];
};
#define F_SMEM ((int)sizeof(SmemF))

__device__ __forceinline__ void mac_segF(
    float2 acc0[4], float2 acc1[4],
    const float4* __restrict__ w0, const float4* __restrict__ w1,
    const float* __restrict__ sv, int kb, int ke)
{
#pragma unroll 4
    for (int k = kb; k < ke; k++) {
        float2 v  = *(const float2*)(sv + (k << 6));
        float2 d0 = make_float2(v.x, v.x);
        float2 d1 = make_float2(v.y, v.y);
        float4 wa = w0[k];
        ffma2(acc0[0], make_float2(wa.x, wa.y), d0);
        ffma2(acc0[1], make_float2(wa.z, wa.w), d0);
        ffma2(acc0[2], make_float2(wa.x, wa.y), d1);
        ffma2(acc0[3], make_float2(wa.z, wa.w), d1);
        float4 wb = w1[k];
        ffma2(acc1[0], make_float2(wb.x, wb.y), d0);
        ffma2(acc1[1], make_float2(wb.z, wb.w), d0);
        ffma2(acc1[2], make_float2(wb.x, wb.y), d1);
        ffma2(acc1[3], make_float2(wb.z, wb.w), d1);
    }
}

__global__ void __launch_bounds__(F_NTHR, 1) lstm_flat(LstmArgs a) {
    extern __shared__ char smem_raw[];
    SmemF* sm = (SmemF*)smem_raw;
    const int bid = blockIdx.x;
    const int tid = threadIdx.x;

    const int ub    = bid >> 2;
    const int grp   = bid & 3;
    const int u0    = ub * 4;
    const int bbase = grp * 64;

    // phase 0
    {
        float (*tile)[33] = (float(*)[33])sm->sh0;
        const int tx = tid & 31, ty = tid >> 5;
        const int ntile = (TDN / 32) * (BN / 32);
        for (int tl = bid; tl < ntile; tl += F_NCTA) {
            int tdBase = (tl % (TDN / 32)) * 32;
            int bBase  = (tl / (TDN / 32)) * 32;
#pragma unroll
            for (int j = 0; j < 4; j++)
                tile[ty + j * 8][tx] =
                    a.x[(size_t)(bBase + ty + j * 8) * TDN + tdBase + tx];
            __syncthreads();
#pragma unroll
            for (int j = 0; j < 4; j++)
                g_xT[(size_t)(tdBase + ty + j * 8) * BN + bBase + tx] =
                    tile[tx][ty + j * 8];
            __syncthreads();
        }
        for (int i = bid * F_NTHR + tid; i < HN * BN; i += F_NCTA * F_NTHR) {
            gf_h0[0][i] = 0.f; gf_h0[1][i] = 0.f;
            gf_h1[0][i] = 0.f; gf_h1[1][i] = 0.f;
        }
        if (bid == 0 && tid < 128)
            *(volatile unsigned*)&g_flagF[tid >> 5][tid & 31] = 0u;

        for (int i = tid; i < 4 * DN; i += F_NTHR) {
            int u = i / DN, k = i - u * DN, r = u0 + u;
            sm->wx[u][k][0] = make_float2(a.Wih0[(0 * HN + r) * DN + k],
                                          a.Wih0[(1 * HN + r) * DN + k]);
            sm->wx[u][k][1] = make_float2(a.Wih0[(2 * HN + r) * DN + k],
                                          a.Wih0[(3 * HN + r) * DN + k]);
        }
        for (int i = tid; i < 4 * HN; i += F_NTHR) {
            int u = i >> 7, k = i & 127, r = u0 + u;
            sm->wh0[u][k][0] = make_float2(a.Whh0[(0 * HN + r) * HN + k],
                                           a.Whh0[(1 * HN + r) * HN + k]);
            sm->wh0[u][k][1] = make_float2(a.Whh0[(2 * HN + r) * HN + k],
                                           a.Whh0[(3 * HN + r) * HN + k]);
            sm->w1i[u][k][0] = make_float2(a.Wih1[(0 * HN + r) * HN + k],
                                           a.Wih1[(1 * HN + r) * HN + k]);
            sm->w1i[u][k][1] = make_float2(a.Wih1[(2 * HN + r) * HN + k],
                                           a.Wih1[(3 * HN + r) * HN + k]);
            sm->w1h[u][k][0] = make_float2(a.Whh1[(0 * HN + r) * HN + k],
                                           a.Whh1[(1 * HN + r) * HN + k]);
            sm->w1h[u][k][1] = make_float2(a.Whh1[(2 * HN + r) * HN + k],
                                           a.Whh1[(3 * HN + r) * HN + k]);
        }
        if (tid < 16) {
            int s = tid >> 3, u = (tid >> 1) & 3, gp = tid & 1, r = u0 + u;
            const float* bi = s ? a.bih1 : a.bih0;
            const float* bh = s ? a.bhh1 : a.bhh0;
            int g0 = gp * 2, g1 = gp * 2 + 1;
            sm->sb[s][u][gp] = make_float2(bi[g0 * HN + r] + bh[g0 * HN + r],
                                           bi[g1 * HN + r] + bh[g1 * HN + r]);
        }
    }
    gbar_full();

    // phase 1
    {
        const int wid  = tid >> 5;
        const int lane = tid & 31;
        const int s    = wid >> 2;
        const int up   = (wid >> 1) & 1;
        const int kh   = wid & 1;
        const int lu0  = up * 2;
        const int b0   = 2 * lane;
        const int ridx = s * 2 + up;

        const int len0 = a.length[bbase + b0];
        const int len1 = a.length[bbase + b0 + 1];

        const float4* wp1u0 = s ? (const float4*)&sm->w1i[lu0][0][0]
                                : (const float4*)&sm->wx [lu0][0][0];
        const float4* wp1u1 = s ? (const float4*)&sm->w1i[lu0 + 1][0][0]
                                : (const float4*)&sm->wx [lu0 + 1][0][0];
        const float4* wp2u0 = s ? (const float4*)&sm->w1h[lu0][0][0]
                                : (const float4*)&sm->wh0[lu0][0][0];
        const float4* wp2u1 = s ? (const float4*)&sm->w1h[lu0 + 1][0][0]
                                : (const float4*)&sm->wh0[lu0 + 1][0][0];
        const float* in1base = s ? sm->sh0 : sm->sx;
        const int kb1 = s ? (kh * 64) : (kh * 20);
        const int ke1 = s ? (kh * 64 + 64) : (kh * 20 + 20);
        const int kb2 = kh * 64, ke2 = kb2 + 64;

        float c00 = 0.f, c01 = 0.f, c10 = 0.f, c11 = 0.f;
        float h00 = 0.f, h01 = 0.f, h10 = 0.f, h11 = 0.f;

#pragma unroll 1
        for (int it = 0; it <= TN; it++) {
            if (it < TN) {
                const float* xsrc = g_xT + (size_t)it * DN * BN + bbase;
                for (int i = tid; i < DN * 16; i += F_NTHR) {
                    int r = i >> 4, j = (i & 15) << 2;
                    *(float4*)(sm->sx + r * 64 + j) =
                        __ldcg((const float4*)(xsrc + (size_t)r * BN + j));
                }
            }
            if (tid < 32)
                while (ldacq(&g_flagF[grp][tid]) < (unsigned)it) { }
            __syncthreads();

            {
                const float* s0 = gf_h0[(it + 1) & 1] + bbase;
                const float* s1 = gf_h1[it & 1] + bbase;
                for (int i = tid; i < HN * 16; i += F_NTHR) {
                    int r = i >> 4, j = (i & 15) << 2;
                    *(float4*)(sm->sh0 + r * 64 + j) =
                        __ldcg((const float4*)(s0 + (size_t)r * BN + j));
                    *(float4*)(sm->sh1 + r * 64 + j) =
                        __ldcg((const float4*)(s1 + (size_t)r * BN + j));
                }
            }
            __syncthreads();

            const bool active = s ? (it >= 1) : (it < TN);
            float2 acc0[4], acc1[4];
            if (active) {
                if (kh == 0) {
#pragma unroll
                    for (int j = 0; j < 4; j++) {
                        acc0[j] = sm->sb[s][lu0][j & 1];
                        acc1[j] = sm->sb[s][lu0 + 1][j & 1];
                    }
                } else {
#pragma unroll
                    for (int j = 0; j < 4; j++) {
                        acc0[j] = make_float2(0.f, 0.f);
                        acc1[j] = make_float2(0.f, 0.f);
                    }
                }
                mac_segF(acc0, acc1, wp1u0, wp1u1, in1base + b0, kb1, ke1);
                mac_segF(acc0, acc1, wp2u0, wp2u1,
                         (s ? sm->sh1 : sm->sh0) + b0, kb2, ke2);
                if (kh == 1) {
#pragma unroll
                    for (int j = 0; j < 4; j++) {
                        sm->red[ridx][lane][j]     = acc0[j];
                        sm->red[ridx][lane][j + 4] = acc1[j];
                    }
                }
            }
            __syncthreads();

            if (active && kh == 0) {
#pragma unroll
                for (int j = 0; j < 4; j++) {
                    float2 p0 = sm->red[ridx][lane][j];
                    float2 p1 = sm->red[ridx][lane][j + 4];
                    acc0[j].x += p0.x; acc0[j].y += p0.y;
                    acc1[j].x += p1.x; acc1[j].y += p1.y;
                }
                const int t = s ? (it - 1) : it;
                {
                    float i_ = sigf(acc0[0].x), f_ = sigf(acc0[0].y);
                    float g_ = tanhx(acc0[1].x), o_ = sigf(acc0[1].y);
                    float cn = f_ * c00 + i_ * g_;
                    float hn = o_ * tanhx(cn);
                    if (t < len0) { c00 = cn; h00 = hn; }
                }
                {
                    float i_ = sigf(acc0[2].x), f_ = sigf(acc0[2].y);
                    float g_ = tanhx(acc0[3].x), o_ = sigf(acc0[3].y);
                    float cn = f_ * c01 + i_ * g_;
                    float hn = o_ * tanhx(cn);
                    if (t < len1) { c01 = cn; h01 = hn; }
                }
                {
                    float i_ = sigf(acc1[0].x), f_ = sigf(acc1[0].y);
                    float g_ = tanhx(acc1[1].x), o_ = sigf(acc1[1].y);
                    float cn = f_ * c10 + i_ * g_;
                    float hn = o_ * tanhx(cn);
                    if (t < len0) { c10 = cn; h10 = hn; }
                }
                {
                    float i_ = sigf(acc1[2].x), f_ = sigf(acc1[2].y);
                    float g_ = tanhx(acc1[3].x), o_ = sigf(acc1[3].y);
                    float cn = f_ * c11 + i_ * g_;
                    float hn = o_ * tanhx(cn);
                    if (t < len1) { c11 = cn; h11 = hn; }
                }
                float* hout = s ? gf_h1[(it + 1) & 1] : gf_h0[it & 1];
                int row = (u0 + lu0) * BN + bbase + b0;
                __stcg((float2*)&hout[row],      make_float2(h00, h01));
                __stcg((float2*)&hout[row + BN], make_float2(h10, h11));
            }
            __syncthreads();
            if (tid == 0) {
                __threadfence();
                strel(&g_flagF[grp][ub], (unsigned)(it + 1));
            }
        }
    }
    gbar_full();

    // phase 2
    {
        float* hv  = sm->sx;
        float* red = sm->sx + 160;
        const int brow = bid * 2;

        for (int rep = 0; rep < 2; rep++) {
            int b = brow + rep;
            float v = (tid < HN)
                ? __ldcg(&gf_h1[(TN - 1) & 1][(size_t)tid * BN + b]) : 0.f;

            float sum = v;
#pragma unroll
            for (int o = 16; o; o >>= 1) sum += __shfl_xor_sync(0xffffffffu, sum, o);
            if ((tid & 31) == 0 && tid < HN) red[tid >> 5] = sum;
            __syncthreads();
            float mu = (red[0] + red[1] + red[2] + red[3]) * (1.0f / HN);

            float d = (tid < HN) ? (v - mu) : 0.f;
            float q = d * d;
#pragma unroll
            for (int o = 16; o; o >>= 1) q += __shfl_xor_sync(0xffffffffu, q, o);
            __syncthreads();
            if ((tid & 31) == 0 && tid < HN) red[tid >> 5] = q;
            __syncthreads();
            float var = (red[0] + red[1] + red[2] + red[3]) * (1.0f / HN);

            if (tid < HN)
                hv[tid] = d * rsqrtf(var + 1e-5f) * a.lng[tid] + a.lnb[tid];
            __syncthreads();

            if (tid < CN) {
                float acc = a.fcb[tid];
#pragma unroll 4
                for (int h = 0; h < HN; h++)
                    acc = fmaf(hv[h], a.fcw[tid * HN + h], acc);
                a.out[b * CN + tid] = acc;
            }
            __syncthreads();
        }
    }
}

// ---------------------------------------------------------------------------
extern "C" void kernel_launch(void* const* d_in, const int* in_sizes, int n_in,
                              void* d_out, int out_size)
{
    LstmArgs a;
    a.x      = (const float*)d_in[0];
    a.length = (const int*)  d_in[1];
    a.Wih0 = (const float*)d_in[2];
    a.Whh0 = (const float*)d_in[3];
    a.bih0 = (const float*)d_in[4];
    a.bhh0 = (const float*)d_in[5];
    a.Wih1 = (const float*)d_in[6];
    a.Whh1 = (const float*)d_in[7];
    a.bih1 = (const float*)d_in[8];
    a.bhh1 = (const float*)d_in[9];
    a.lng  = (const float*)d_in[10];
    a.lnb  = (const float*)d_in[11];
    a.fcw  = (const float*)d_in[12];
    a.fcb  = (const float*)d_in[13];
    a.out  = (float*)d_out;

    static bool attr_done = false;
    if (!attr_done) {
        cudaFuncSetAttribute(lstm_cluster,
                             cudaFuncAttributeMaxDynamicSharedMemorySize, C_SMEM);
        cudaFuncSetAttribute(lstm_flat,
                             cudaFuncAttributeMaxDynamicSharedMemorySize, F_SMEM);
        attr_done = true;
    }

    // Cluster feasibility check (host-side query; deterministic per device).
    cudaLaunchConfig_t cfg = {};
    cfg.gridDim  = dim3(C_NCTA, 1, 1);
    cfg.blockDim = dim3(C_NTHR, 1, 1);
    cfg.dynamicSmemBytes = C_SMEM;
    cfg.stream = 0;
    cudaLaunchAttribute attrs[1];
    attrs[0].id = cudaLaunchAttributeClusterDimension;
    attrs[0].val.clusterDim.x = CSIZE;
    attrs[0].val.clusterDim.y = 1;
    attrs[0].val.clusterDim.z = 1;
    cfg.attrs = attrs;
    cfg.numAttrs = 1;

    int nclust = 0;
    cudaError_t qe = cudaOccupancyMaxActiveClusters(&nclust, lstm_cluster, &cfg);
    bool launched = false;
    if (qe == cudaSuccess && nclust >= 1) {
        cudaError_t le = cudaLaunchKernelEx(&cfg, lstm_cluster, a);
        launched = (le == cudaSuccess);
    }
    if (!launched) {
        (void)cudaGetLastError();   // clear non-sticky config error
        lstm_flat<<<F_NCTA, F_NTHR, F_SMEM>>>(a);
    }
}